// round 14
// baseline (speedup 1.0000x reference)
#include <cuda_runtime.h>
#include <cuda_fp16.h>
#include <math.h>
#include <stdint.h>

#define BATCH 16
#define CCH   512
#define NSP   4096
#define NGRP  16

// Scratch (device globals: allocation-free per harness rules)
__device__ __half g_o116[(size_t)BATCH * CCH * NSP];  // attention output fp16 [e][n]
__device__ __half g_xn16[(size_t)BATCH * CCH * NSP];  // gn1(x) fp16 [c][n] (residual)
__device__ __half g_v16 [(size_t)BATCH * CCH * NSP];  // v fp16 [e][n]
__device__ __half g_E16 [(size_t)BATCH * CCH * NSP];  // exp(k+bias) fp16 [d][n]
__device__ __half g_h16 [(size_t)BATCH * CCH * NSP];  // gelu(gn2(o1)) fp16 [c][n]
__device__ __half g_ctx16[(size_t)BATCH * CCH * CCH]; // ctx2 [e][d]
__device__ float  g_rsinv[BATCH * CCH];               // 1 / spatial rowsum
__device__ float  g_csinv[BATCH * NSP];               // scale / channel colsum
__device__ float2 g_part [BATCH * NGRP * 8];          // gn partial stats
__device__ float2 g_stats1[BATCH * NGRP];             // gn1 (mean, inv)
__device__ float2 g_stats2[BATCH * NGRP];             // gn2 (mean, inv)
__device__ unsigned g_cnt1 = 0, g_cnt2 = 0;           // last-block tickets (self-reset)
__device__ __half g_w16 [1024 * 512 + 512 * 512];     // kvw16, ow16

// ---------------------------------------------------------------------------
__device__ __forceinline__ uint32_t smem_u32(const void* p) {
    uint32_t a;
    asm("{ .reg .u64 t; cvta.to.shared.u64 t, %1; cvt.u32.u64 %0, t; }" : "=r"(a) : "l"(p));
    return a;
}
__device__ __forceinline__ void cp16(uint32_t dst, const void* src) {
    asm volatile("cp.async.cg.shared.global [%0], [%1], 16;" :: "r"(dst), "l"(src) : "memory");
}
__device__ __forceinline__ void ldsm4(uint32_t& r0, uint32_t& r1, uint32_t& r2, uint32_t& r3,
                                      uint32_t addr) {
    asm volatile("ldmatrix.sync.aligned.m8n8.x4.shared.b16 {%0,%1,%2,%3}, [%4];"
                 : "=r"(r0), "=r"(r1), "=r"(r2), "=r"(r3) : "r"(addr));
}
__device__ __forceinline__ void ldsm4t(uint32_t& r0, uint32_t& r1, uint32_t& r2, uint32_t& r3,
                                       uint32_t addr) {
    asm volatile("ldmatrix.sync.aligned.m8n8.x4.trans.shared.b16 {%0,%1,%2,%3}, [%4];"
                 : "=r"(r0), "=r"(r1), "=r"(r2), "=r"(r3) : "r"(addr));
}

// ---------------------------------------------------------------------------
// Fused GN stats: partial sums + last-block reduce (self-resetting counter).
// ---------------------------------------------------------------------------
__device__ __forceinline__ void gn_finish(float2* __restrict__ part,
                                          float2* __restrict__ stats,
                                          unsigned* cnt, int bx, int tid,
                                          float s, float s2)
{
    __shared__ float sh1[256], sh2[256];
    sh1[tid] = s; sh2[tid] = s2;
    __syncthreads();
    for (int o = 128; o > 0; o >>= 1) {
        if (tid < o) { sh1[tid] += sh1[tid + o]; sh2[tid] += sh2[tid + o]; }
        __syncthreads();
    }
    if (tid == 0) part[bx] = make_float2(sh1[0], sh2[0]);
    __threadfence();
    __shared__ unsigned lastf;
    if (tid == 0) lastf = (atomicAdd(cnt, 1u) == (unsigned)(BATCH * NGRP * 8 - 1));
    __syncthreads();
    if (lastf) {
        float rs = 0.f, rs2 = 0.f;
#pragma unroll
        for (int j = 0; j < 8; j++) {
            float2 p = part[tid * 8 + j];
            rs += p.x; rs2 += p.y;
        }
        const float GE = 32.f * NSP;
        float mean = rs / GE;
        float var  = rs2 / GE - mean * mean;
        stats[tid] = make_float2(mean, rsqrtf(var + 1e-5f));
        if (tid == 0) *cnt = 0;
    }
}

__global__ void gstats32(const float* __restrict__ x, float2* __restrict__ part,
                         float2* __restrict__ stats, unsigned* cnt)
{
    const int bx = blockIdx.x;
    const size_t base = (size_t)(bx >> 3) * 32 * NSP + (size_t)(bx & 7) * 512;
    const int tid = threadIdx.x;
    float s = 0.f, s2 = 0.f;
#pragma unroll 4
    for (int i = 0; i < 16; i++) {
        int id = i * 256 + tid;
        int r = id >> 7, c4 = id & 127;
        float4 v = *(const float4*)(x + base + (size_t)r * NSP + c4 * 4);
        s  += v.x + v.y + v.z + v.w;
        s2 += v.x * v.x + v.y * v.y + v.z * v.z + v.w * v.w;
    }
    gn_finish(part, stats, cnt, bx, tid, s, s2);
}

__global__ void gstats16(const __half* __restrict__ x, float2* __restrict__ part,
                         float2* __restrict__ stats, unsigned* cnt)
{
    const int bx = blockIdx.x;
    const size_t base = (size_t)(bx >> 3) * 32 * NSP + (size_t)(bx & 7) * 512;
    const int tid = threadIdx.x;
    float s = 0.f, s2 = 0.f;
#pragma unroll 4
    for (int i = 0; i < 8; i++) {
        int id = i * 256 + tid;
        int r = id >> 6, c8 = id & 63;
        uint4 u = *(const uint4*)(x + base + (size_t)r * NSP + c8 * 8);
        float2 fa = __half22float2(*(__half2*)&u.x);
        float2 fb = __half22float2(*(__half2*)&u.y);
        float2 fc = __half22float2(*(__half2*)&u.z);
        float2 fd = __half22float2(*(__half2*)&u.w);
        s  += fa.x + fa.y + fb.x + fb.y + fc.x + fc.y + fd.x + fd.y;
        s2 += fa.x * fa.x + fa.y * fa.y + fb.x * fb.x + fb.y * fb.y +
              fc.x * fc.x + fc.y * fc.y + fd.x * fd.x + fd.y * fd.y;
    }
    gn_finish(part, stats, cnt, bx, tid, s, s2);
}

// ---------------------------------------------------------------------------
// GN normalize (+gelu) -> fp16 same layout.
// ---------------------------------------------------------------------------
template <typename Tin, int GELU>
__global__ void gnorm(const Tin* __restrict__ x, const float* __restrict__ w,
                      const float* __restrict__ b, const float2* __restrict__ stats,
                      __half* __restrict__ y)
{
    const int bx = blockIdx.x;
    const int grp = bx >> 3;
    const int cbase = (grp & 15) << 5;
    const size_t base = (size_t)grp * 32 * NSP + (size_t)(bx & 7) * 512;
    const int tid = threadIdx.x;
    float2 st = stats[grp];

#pragma unroll 2
    for (int i = 0; i < 16; i++) {
        int id = i * 256 + tid;
        int r = id >> 7, c4 = id & 127;
        float sc = w[cbase + r] * st.y;
        float of = b[cbase + r] - st.x * sc;
        size_t off = base + (size_t)r * NSP + c4 * 4;
        float4 v;
        if (sizeof(Tin) == 4) {
            v = *(const float4*)((const float*)x + off);
        } else {
            uint2 u = *(const uint2*)((const __half*)x + off);
            float2 f0 = __half22float2(*(__half2*)&u.x);
            float2 f1 = __half22float2(*(__half2*)&u.y);
            v = make_float4(f0.x, f0.y, f1.x, f1.y);
        }
        v.x = v.x * sc + of; v.y = v.y * sc + of;
        v.z = v.z * sc + of; v.w = v.w * sc + of;
        if (GELU) {
            v.x = 0.5f * v.x * (1.0f + erff(v.x * 0.70710678f));
            v.y = 0.5f * v.y * (1.0f + erff(v.y * 0.70710678f));
            v.z = 0.5f * v.z * (1.0f + erff(v.z * 0.70710678f));
            v.w = 0.5f * v.w * (1.0f + erff(v.w * 0.70710678f));
        }
        __half2* o2 = (__half2*)(y + off);
        o2[0] = __floats2half2_rn(v.x, v.y);
        o2[1] = __floats2half2_rn(v.z, v.w);
    }
}

// ---------------------------------------------------------------------------
// Spatial rowsum of E16 -> 1/sum.
// ---------------------------------------------------------------------------
__global__ void rowsum_k(const __half* __restrict__ E, float* __restrict__ rsinv)
{
    const size_t off = (size_t)blockIdx.x * NSP;
    const uint4* p = (const uint4*)(E + off);
    const int tid = threadIdx.x;
    float s = 0.f;
#pragma unroll
    for (int i = tid; i < NSP / 8; i += 256) {
        uint4 u = p[i];
        float2 fa = __half22float2(*(__half2*)&u.x);
        float2 fb = __half22float2(*(__half2*)&u.y);
        float2 fc = __half22float2(*(__half2*)&u.z);
        float2 fd = __half22float2(*(__half2*)&u.w);
        s += fa.x + fa.y + fb.x + fb.y + fc.x + fc.y + fd.x + fd.y;
    }
    __shared__ float sh[256];
    sh[tid] = s; __syncthreads();
    for (int o = 128; o > 0; o >>= 1) {
        if (tid < o) sh[tid] += sh[tid + o];
        __syncthreads();
    }
    if (tid == 0) rsinv[blockIdx.x] = 1.0f / sh[0];
}

// ---------------------------------------------------------------------------
// Channel colsum of E16: csinv[b][n] = scale / sum_d E[d][n].
// ---------------------------------------------------------------------------
__global__ void colsum(const __half* __restrict__ E, float* __restrict__ csinv,
                       float scale)
{
    const int bb = blockIdx.x >> 3;
    const int n0 = (blockIdx.x & 7) * 512;
    const __half* p = E + (size_t)bb * CCH * NSP + n0 + 2 * threadIdx.x;
    float s0 = 0.f, s1 = 0.f;
    for (int d = 0; d < CCH; d++) {
        float2 f = __half22float2(*(const __half2*)&p[(size_t)d * NSP]);
        s0 += f.x; s1 += f.y;
    }
    float* c = csinv + bb * NSP + n0 + 2 * threadIdx.x;
    c[0] = scale / s0;
    c[1] = scale / s1;
}

// ---------------------------------------------------------------------------
// Flat fp32 -> fp16 convert (weights only).
// ---------------------------------------------------------------------------
__global__ void cvt16(const float* __restrict__ in, __half* __restrict__ out, size_t n4)
{
    size_t stride = (size_t)gridDim.x * blockDim.x;
    const float4* in4 = (const float4*)in;
    __half2* o2 = (__half2*)out;
    for (size_t i = (size_t)blockIdx.x * blockDim.x + threadIdx.x; i < n4; i += stride) {
        float4 v = in4[i];
        o2[2 * i]     = __floats2half2_rn(v.x, v.y);
        o2[2 * i + 1] = __floats2half2_rn(v.z, v.w);
    }
}

// ---------------------------------------------------------------------------
// fp16 mma.sync (m16n8k16) GEMM — BIG-TILE variant.
// Block tile 128(M) x 256(N) x 32(K), 256 threads = 8 warps (2m x 4n),
// warp tile 64x64 (halves LDSM redundancy: shared:tensor = 1:2).
// 3-stage cp.async, dynamic smem (A 10240B + B 20480/16896B per stage).
// C[m,n] = sum_k A[m,k]*B(n,k)  (+bias[m]) (+resh fp16) (*cscale[n])
// KV: rows<512 -> E16=exp(.) ; rows>=512 -> v16. TB: B K-major via ldsm.trans.
// ---------------------------------------------------------------------------
#define STGA 10240
#define BSTG_N 20480   // non-TB: 256 rows * 80B
#define BSTG_T 16896   // TB: 32 k-rows * 528B

template <bool KV, bool TB, bool C_HALF, bool HAS_BIAS, bool RESH, bool CSCALE>
__global__ __launch_bounds__(256, 1)
void gemm_fp16(const __half* __restrict__ A, const __half* __restrict__ B,
               void* __restrict__ Cv, __half* __restrict__ C2,
               const float* __restrict__ bias,
               const __half* __restrict__ resh,
               const float* __restrict__ cscale, int csStride,
               int lda, int ldb, int ldc, int K,
               size_t sA, size_t sB, size_t sC, size_t sC2)
{
    constexpr int BSTG = TB ? BSTG_T : BSTG_N;
    extern __shared__ __half dsm[];

    A += (size_t)blockIdx.z * sA;
    B += (size_t)blockIdx.z * sB;
    if (RESH)   resh   += (size_t)blockIdx.z * sC;
    if (CSCALE) cscale += (size_t)blockIdx.z * csStride;

    const int tid  = threadIdx.x;
    const int lane = tid & 31;
    const int warp = tid >> 5;
    const int g = lane >> 2;
    const int t = lane & 3;
    const int wm = (warp & 1) * 64;
    const int wn = (warp >> 1) * 64;
    const int m0 = blockIdx.y * 128;
    const int n0 = blockIdx.x * 256;

    const uint32_t aBase = smem_u32(dsm);
    const uint32_t bBase = aBase + 3 * STGA;

    const uint32_t aOff = (uint32_t)(wm + (lane & 15)) * 80 + (lane >> 4) * 16;
    const uint32_t bOff = (uint32_t)(wn + (lane & 7) + ((lane >> 4) << 3)) * 80 +
                          ((lane >> 3) & 1) * 16;
    const uint32_t bOffT = (uint32_t)((lane & 7) + ((lane >> 3) & 1) * 8) * 528 +
                           (lane >> 4) * 16;

    float acc[4][8][4];
#pragma unroll
    for (int i = 0; i < 4; i++)
#pragma unroll
        for (int j = 0; j < 8; j++)
#pragma unroll
            for (int r = 0; r < 4; r++) acc[i][j][r] = 0.f;

    auto load_tile = [&](int k0, int st) {
        uint32_t ab = aBase + st * STGA;
        uint32_t bb = bBase + st * BSTG;
#pragma unroll
        for (int i = 0; i < 2; i++) {
            int id = i * 256 + tid;
            int r = id >> 2, c = id & 3;
            cp16(ab + r * 80 + c * 16, A + (size_t)(m0 + r) * lda + k0 + c * 8);
        }
#pragma unroll
        for (int i = 0; i < 4; i++) {
            int id = i * 256 + tid;
            if (TB) {
                int r = id >> 5, c = id & 31;   // 32 k-rows x 32 chunks of 16B
                cp16(bb + r * 528 + c * 16, B + (size_t)(k0 + r) * ldb + n0 + c * 8);
            } else {
                int r = id >> 2, c = id & 3;    // 256 n-rows x 4 chunks
                cp16(bb + r * 80 + c * 16, B + (size_t)(n0 + r) * ldb + k0 + c * 8);
            }
        }
        asm volatile("cp.async.commit_group;" ::: "memory");
    };

    const int T = K / 32;
    load_tile(0, 0);
    if (T > 1) load_tile(32, 1);

    for (int tt = 0; tt < T; tt++) {
        if (tt + 2 < T) asm volatile("cp.async.wait_group 1;" ::: "memory");
        else            asm volatile("cp.async.wait_group 0;" ::: "memory");
        __syncthreads();

        if (tt + 2 < T) load_tile((tt + 2) * 32, (tt + 2) % 3);

        const int st = tt % 3;
        const uint32_t sa = aBase + st * STGA;
        const uint32_t sb = bBase + st * BSTG;

#pragma unroll
        for (int kk = 0; kk < 2; kk++) {
            uint32_t af[4][4], bf[8][2];
#pragma unroll
            for (int im = 0; im < 4; im++)
                ldsm4(af[im][0], af[im][1], af[im][2], af[im][3],
                      sa + aOff + im * 1280 + kk * 32);
            if (TB) {
#pragma unroll
                for (int p = 0; p < 4; p++)
                    ldsm4t(bf[2 * p][0], bf[2 * p][1], bf[2 * p + 1][0], bf[2 * p + 1][1],
                           sb + bOffT + kk * 8448 + (wn + p * 16) * 2);
            } else {
#pragma unroll
                for (int p = 0; p < 4; p++)
                    ldsm4(bf[2 * p][0], bf[2 * p][1], bf[2 * p + 1][0], bf[2 * p + 1][1],
                          sb + bOff + p * 1280 + kk * 32);
            }
#pragma unroll
            for (int im = 0; im < 4; im++)
#pragma unroll
                for (int in = 0; in < 8; in++) {
                    asm volatile(
                        "mma.sync.aligned.m16n8k16.row.col.f32.f16.f16.f32 "
                        "{%0,%1,%2,%3},{%4,%5,%6,%7},{%8,%9},{%0,%1,%2,%3};\n"
                        : "+f"(acc[im][in][0]), "+f"(acc[im][in][1]),
                          "+f"(acc[im][in][2]), "+f"(acc[im][in][3])
                        : "r"(af[im][0]), "r"(af[im][1]), "r"(af[im][2]), "r"(af[im][3]),
                          "r"(bf[in][0]), "r"(bf[in][1]));
                }
        }
    }

    // epilogue
    const bool isv = KV && (m0 >= 512);
    const bool isk = KV && (m0 < 512);
#pragma unroll
    for (int im = 0; im < 4; im++) {
        int r0 = m0 + wm + im * 16 + g;
        int r1 = r0 + 8;
        float bv0 = HAS_BIAS ? bias[r0] : 0.f;
        float bv1 = HAS_BIAS ? bias[r1] : 0.f;
#pragma unroll
        for (int in = 0; in < 8; in++) {
            int c0 = n0 + wn + in * 8 + 2 * t;
            float v0 = acc[im][in][0] + bv0;
            float v1 = acc[im][in][1] + bv0;
            float v2 = acc[im][in][2] + bv1;
            float v3 = acc[im][in][3] + bv1;
            if (CSCALE) {
                float2 cs = *reinterpret_cast<const float2*>(&cscale[c0]);
                v0 *= cs.x; v1 *= cs.y; v2 *= cs.x; v3 *= cs.y;
            }
            if (isk) {
                v0 = __expf(v0); v1 = __expf(v1);
                v2 = __expf(v2); v3 = __expf(v3);
            }
            if (C_HALF || isv) {
                __half* C16 = ((KV && isv) ? C2 + (size_t)blockIdx.z * sC2
                                           : (__half*)Cv + (size_t)blockIdx.z * sC);
                int rr0 = isv ? r0 - 512 : r0;
                int rr1 = isv ? r1 - 512 : r1;
                *reinterpret_cast<__half2*>(&C16[(size_t)rr0 * ldc + c0]) = __floats2half2_rn(v0, v1);
                *reinterpret_cast<__half2*>(&C16[(size_t)rr1 * ldc + c0]) = __floats2half2_rn(v2, v3);
            } else {
                float* C = (float*)Cv + (size_t)blockIdx.z * sC;
                if (RESH) {
                    float2 x0 = __half22float2(*(const __half2*)&resh[(size_t)r0 * ldc + c0]);
                    float2 x1 = __half22float2(*(const __half2*)&resh[(size_t)r1 * ldc + c0]);
                    v0 += x0.x; v1 += x0.y; v2 += x1.x; v3 += x1.y;
                }
                *reinterpret_cast<float2*>(&C[(size_t)r0 * ldc + c0]) = make_float2(v0, v1);
                *reinterpret_cast<float2*>(&C[(size_t)r1 * ldc + c0]) = make_float2(v2, v3);
            }
        }
    }
}

// ---------------------------------------------------------------------------
extern "C" void kernel_launch(void* const* d_in, const int* in_sizes, int n_in,
                              void* d_out, int out_size)
{
    const float* x   = (const float*)d_in[0];
    const float* n1w = (const float*)d_in[1];
    const float* n1b = (const float*)d_in[2];
    const float* kvw = (const float*)d_in[3];
    const float* kvb = (const float*)d_in[4];
    const float* n2w = (const float*)d_in[5];
    const float* n2b = (const float*)d_in[6];
    const float* ow  = (const float*)d_in[7];
    const float* ob  = (const float*)d_in[8];
    float* out = (float*)d_out;

    float *rsinv, *csinv;
    float2 *part, *stats1, *stats2;
    unsigned *cnt1, *cnt2;
    __half *o116, *xn16, *v16, *E16, *h16, *ctx16, *w16;
    cudaGetSymbolAddress((void**)&o116,   g_o116);
    cudaGetSymbolAddress((void**)&xn16,   g_xn16);
    cudaGetSymbolAddress((void**)&v16,    g_v16);
    cudaGetSymbolAddress((void**)&E16,    g_E16);
    cudaGetSymbolAddress((void**)&h16,    g_h16);
    cudaGetSymbolAddress((void**)&ctx16,  g_ctx16);
    cudaGetSymbolAddress((void**)&rsinv,  g_rsinv);
    cudaGetSymbolAddress((void**)&csinv,  g_csinv);
    cudaGetSymbolAddress((void**)&part,   g_part);
    cudaGetSymbolAddress((void**)&stats1, g_stats1);
    cudaGetSymbolAddress((void**)&stats2, g_stats2);
    cudaGetSymbolAddress((void**)&cnt1,   g_cnt1);
    cudaGetSymbolAddress((void**)&cnt2,   g_cnt2);
    cudaGetSymbolAddress((void**)&w16,    g_w16);

    __half* kvw16 = w16;
    __half* ow16  = w16 + 1024 * 512;

    const size_t sXN  = (size_t)CCH * NSP;
    const size_t sCTX = (size_t)CCH * CCH;
    const int NBLK = BATCH * NGRP * 8;  // 2048
    const int SM_TB = 3 * (STGA + BSTG_T);   // 81408
    const int SM_NT = 3 * (STGA + BSTG_N);   // 92160

    // opt into >48KB dynamic smem (idempotent)
    cudaFuncSetAttribute(gemm_fp16<true,  true,  true,  true,  false, false>,
                         cudaFuncAttributeMaxDynamicSharedMemorySize, SM_TB);
    cudaFuncSetAttribute(gemm_fp16<false, false, true,  false, false, true >,
                         cudaFuncAttributeMaxDynamicSharedMemorySize, SM_NT);
    cudaFuncSetAttribute(gemm_fp16<false, true,  true,  false, false, true >,
                         cudaFuncAttributeMaxDynamicSharedMemorySize, SM_TB);
    cudaFuncSetAttribute(gemm_fp16<false, true,  false, true,  true,  false>,
                         cudaFuncAttributeMaxDynamicSharedMemorySize, SM_TB);

    // 0. weight converts
    cvt16<<<256, 256>>>(kvw, kvw16, (1024 * 512) / 4);
    cvt16<<<128, 256>>>(ow,  ow16,  (512 * 512) / 4);

    // 1. GroupNorm1 -> xn16 [c][n] fp16 (stats fused)
    gstats32<<<NBLK, 256>>>(x, part, stats1, cnt1);
    gnorm<float, 0><<<NBLK, 256>>>(x, n1w, n1b, stats1, xn16);

    // 2. kv GEMM (TB, KV): E16 = exp(k+bias); v16 split. M=1024,N=4096,K=512
    gemm_fp16<true, true, true, true, false, false>
        <<<dim3(NSP / 256, 1024 / 128, BATCH), 256, SM_TB>>>(
        kvw16, xn16, E16, v16, kvb, nullptr, nullptr, 0,
        CCH, NSP, NSP, CCH, 0, sXN, sXN, sXN);

    // 3. rowsum -> 1/sum ; colsum -> scale/sum
    rowsum_k<<<BATCH * CCH, 256>>>(E16, rsinv);
    colsum<<<BATCH * 8, 256>>>(E16, csinv, 0.044194173824159216f);

    // 4. ctx2[e,d] = (sum_n v[e,n]*E[d,n]) * rsinv[d]  -> fp16
    gemm_fp16<false, false, true, false, false, true>
        <<<dim3(CCH / 256, CCH / 128, BATCH), 256, SM_NT>>>(
        v16, E16, ctx16, nullptr, nullptr, nullptr, rsinv, CCH,
        NSP, NSP, CCH, NSP, sXN, sXN, sCTX, 0);

    // 5. o1[e,n] = (sum_d ctx2[e,d]*E[d,n]) * csinv[n]  -> fp16 (TB + CSCALE)
    gemm_fp16<false, true, true, false, false, true>
        <<<dim3(NSP / 256, CCH / 128, BATCH), 256, SM_TB>>>(
        ctx16, E16, o116, nullptr, nullptr, nullptr, csinv, NSP,
        CCH, NSP, NSP, CCH, sCTX, sXN, sXN, 0);

    // 6. h = gelu(GN2(o1)) -> h16 [c][n] (stats fused)
    gstats16<<<NBLK, 256>>>(o116, part, stats2, cnt2);
    gnorm<__half, 1><<<NBLK, 256>>>(o116, n2w, n2b, stats2, h16);

    // 7. out = W_out @ h + b_out + xn16 (fp16 residual)
    gemm_fp16<false, true, false, true, true, false>
        <<<dim3(NSP / 256, CCH / 128, BATCH), 256, SM_TB>>>(
        ow16, h16, out, nullptr, ob, xn16, nullptr, 0,
        CCH, NSP, NSP, CCH, 0, sXN, sXN, 0);
}

// round 15
// speedup vs baseline: 1.1171x; 1.1171x over previous
#include <cuda_runtime.h>
#include <cuda_fp16.h>
#include <math.h>
#include <stdint.h>

#define BATCH 16
#define CCH   512
#define NSP   4096
#define NGRP  16

// Scratch (device globals: allocation-free per harness rules)
__device__ __half g_o116[(size_t)BATCH * CCH * NSP];  // attention output fp16 [e][n]
__device__ __half g_xn16[(size_t)BATCH * CCH * NSP];  // gn1(x) fp16 [c][n] (residual)
__device__ __half g_v16 [(size_t)BATCH * CCH * NSP];  // v fp16 [e][n]
__device__ __half g_E16 [(size_t)BATCH * CCH * NSP];  // exp(k+bias) fp16 [d][n]
__device__ __half g_h16 [(size_t)BATCH * CCH * NSP];  // x16 (step 1), later h16 (step 6)
__device__ __half g_ctx16[(size_t)BATCH * CCH * CCH]; // ctx2 [e][d]
__device__ float  g_rsinv[BATCH * CCH];               // 1 / spatial rowsum
__device__ float  g_csinv[BATCH * NSP];               // scale / channel colsum
__device__ float2 g_part [BATCH * NGRP * 8];          // gn partial stats
__device__ float2 g_stats1[BATCH * NGRP];             // gn1 (mean, inv)
__device__ float2 g_stats2[BATCH * NGRP];             // gn2 (mean, inv)
__device__ unsigned g_cnt1 = 0, g_cnt2 = 0;           // last-block tickets (self-reset)
__device__ __half g_w16 [1024 * 512 + 512 * 512];     // kvw16, ow16

// ---------------------------------------------------------------------------
__device__ __forceinline__ uint32_t smem_u32(const void* p) {
    uint32_t a;
    asm("{ .reg .u64 t; cvta.to.shared.u64 t, %1; cvt.u32.u64 %0, t; }" : "=r"(a) : "l"(p));
    return a;
}
__device__ __forceinline__ void cp16(uint32_t dst, const void* src) {
    asm volatile("cp.async.cg.shared.global [%0], [%1], 16;" :: "r"(dst), "l"(src) : "memory");
}
__device__ __forceinline__ void ldsm4(uint32_t& r0, uint32_t& r1, uint32_t& r2, uint32_t& r3,
                                      uint32_t addr) {
    asm volatile("ldmatrix.sync.aligned.m8n8.x4.shared.b16 {%0,%1,%2,%3}, [%4];"
                 : "=r"(r0), "=r"(r1), "=r"(r2), "=r"(r3) : "r"(addr));
}
__device__ __forceinline__ void ldsm4t(uint32_t& r0, uint32_t& r1, uint32_t& r2, uint32_t& r3,
                                       uint32_t addr) {
    asm volatile("ldmatrix.sync.aligned.m8n8.x4.trans.shared.b16 {%0,%1,%2,%3}, [%4];"
                 : "=r"(r0), "=r"(r1), "=r"(r2), "=r"(r3) : "r"(addr));
}

// ---------------------------------------------------------------------------
// Fused GN stats: partial sums + last-block reduce (self-resetting counter).
// ---------------------------------------------------------------------------
__device__ __forceinline__ void gn_finish(float2* __restrict__ part,
                                          float2* __restrict__ stats,
                                          unsigned* cnt, int bx, int tid,
                                          float s, float s2)
{
    __shared__ float sh1[256], sh2[256];
    sh1[tid] = s; sh2[tid] = s2;
    __syncthreads();
    for (int o = 128; o > 0; o >>= 1) {
        if (tid < o) { sh1[tid] += sh1[tid + o]; sh2[tid] += sh2[tid + o]; }
        __syncthreads();
    }
    if (tid == 0) part[bx] = make_float2(sh1[0], sh2[0]);
    __threadfence();
    __shared__ unsigned lastf;
    if (tid == 0) lastf = (atomicAdd(cnt, 1u) == (unsigned)(BATCH * NGRP * 8 - 1));
    __syncthreads();
    if (lastf) {
        float rs = 0.f, rs2 = 0.f;
#pragma unroll
        for (int j = 0; j < 8; j++) {
            float2 p = part[tid * 8 + j];
            rs += p.x; rs2 += p.y;
        }
        const float GE = 32.f * NSP;
        float mean = rs / GE;
        float var  = rs2 / GE - mean * mean;
        stats[tid] = make_float2(mean, rsqrtf(var + 1e-5f));
        if (tid == 0) *cnt = 0;
    }
}

// gn1 stats over fp32 x + emit fp16 copy of x (for the normalize pass).
__global__ void gstats32(const float* __restrict__ x, __half* __restrict__ x16,
                         float2* __restrict__ part, float2* __restrict__ stats,
                         unsigned* cnt)
{
    const int bx = blockIdx.x;
    const size_t base = (size_t)(bx >> 3) * 32 * NSP + (size_t)(bx & 7) * 512;
    const int tid = threadIdx.x;
    float s = 0.f, s2 = 0.f;
#pragma unroll 4
    for (int i = 0; i < 16; i++) {
        int id = i * 256 + tid;
        int r = id >> 7, c4 = id & 127;
        size_t off = base + (size_t)r * NSP + c4 * 4;
        float4 v = *(const float4*)(x + off);
        s  += v.x + v.y + v.z + v.w;
        s2 += v.x * v.x + v.y * v.y + v.z * v.z + v.w * v.w;
        __half2* o2 = (__half2*)(x16 + off);
        o2[0] = __floats2half2_rn(v.x, v.y);
        o2[1] = __floats2half2_rn(v.z, v.w);
    }
    gn_finish(part, stats, cnt, bx, tid, s, s2);
}

__global__ void gstats16(const __half* __restrict__ x, float2* __restrict__ part,
                         float2* __restrict__ stats, unsigned* cnt)
{
    const int bx = blockIdx.x;
    const size_t base = (size_t)(bx >> 3) * 32 * NSP + (size_t)(bx & 7) * 512;
    const int tid = threadIdx.x;
    float s = 0.f, s2 = 0.f;
#pragma unroll 4
    for (int i = 0; i < 8; i++) {
        int id = i * 256 + tid;
        int r = id >> 6, c8 = id & 63;
        uint4 u = *(const uint4*)(x + base + (size_t)r * NSP + c8 * 8);
        float2 fa = __half22float2(*(__half2*)&u.x);
        float2 fb = __half22float2(*(__half2*)&u.y);
        float2 fc = __half22float2(*(__half2*)&u.z);
        float2 fd = __half22float2(*(__half2*)&u.w);
        s  += fa.x + fa.y + fb.x + fb.y + fc.x + fc.y + fd.x + fd.y;
        s2 += fa.x * fa.x + fa.y * fa.y + fb.x * fb.x + fb.y * fb.y +
              fc.x * fc.x + fc.y * fc.y + fd.x * fd.x + fd.y * fd.y;
    }
    gn_finish(part, stats, cnt, bx, tid, s, s2);
}

// ---------------------------------------------------------------------------
// GN normalize (+gelu), fp16 in -> fp16 out, same layout.
// ---------------------------------------------------------------------------
template <int GELU>
__global__ void gnorm16(const __half* __restrict__ x, const float* __restrict__ w,
                        const float* __restrict__ b, const float2* __restrict__ stats,
                        __half* __restrict__ y)
{
    const int bx = blockIdx.x;
    const int grp = bx >> 3;
    const int cbase = (grp & 15) << 5;
    const size_t base = (size_t)grp * 32 * NSP + (size_t)(bx & 7) * 512;
    const int tid = threadIdx.x;
    float2 st = stats[grp];

#pragma unroll 2
    for (int i = 0; i < 8; i++) {
        int id = i * 256 + tid;
        int r = id >> 6, c8 = id & 63;
        float sc = w[cbase + r] * st.y;
        float of = b[cbase + r] - st.x * sc;
        size_t off = base + (size_t)r * NSP + c8 * 8;
        uint4 u = *(const uint4*)(x + off);
        float2 f[4];
        f[0] = __half22float2(*(__half2*)&u.x);
        f[1] = __half22float2(*(__half2*)&u.y);
        f[2] = __half22float2(*(__half2*)&u.z);
        f[3] = __half22float2(*(__half2*)&u.w);
        uint4 o;
        uint32_t* op = (uint32_t*)&o;
#pragma unroll
        for (int j = 0; j < 4; j++) {
            float a0 = f[j].x * sc + of;
            float a1 = f[j].y * sc + of;
            if (GELU) {
                a0 = 0.5f * a0 * (1.0f + erff(a0 * 0.70710678f));
                a1 = 0.5f * a1 * (1.0f + erff(a1 * 0.70710678f));
            }
            __half2 h = __floats2half2_rn(a0, a1);
            op[j] = *(uint32_t*)&h;
        }
        *(uint4*)(y + off) = o;
    }
}

// ---------------------------------------------------------------------------
// Spatial rowsum of E16 -> 1/sum.
// ---------------------------------------------------------------------------
__global__ void rowsum_k(const __half* __restrict__ E, float* __restrict__ rsinv)
{
    const size_t off = (size_t)blockIdx.x * NSP;
    const uint4* p = (const uint4*)(E + off);
    const int tid = threadIdx.x;
    float s = 0.f;
#pragma unroll
    for (int i = tid; i < NSP / 8; i += 256) {
        uint4 u = p[i];
        float2 fa = __half22float2(*(__half2*)&u.x);
        float2 fb = __half22float2(*(__half2*)&u.y);
        float2 fc = __half22float2(*(__half2*)&u.z);
        float2 fd = __half22float2(*(__half2*)&u.w);
        s += fa.x + fa.y + fb.x + fb.y + fc.x + fc.y + fd.x + fd.y;
    }
    __shared__ float sh[256];
    sh[tid] = s; __syncthreads();
    for (int o = 128; o > 0; o >>= 1) {
        if (tid < o) sh[tid] += sh[tid + o];
        __syncthreads();
    }
    if (tid == 0) rsinv[blockIdx.x] = 1.0f / sh[0];
}

// ---------------------------------------------------------------------------
// Channel colsum of E16: csinv[b][n] = scale / sum_d E[d][n].
// ---------------------------------------------------------------------------
__global__ void colsum(const __half* __restrict__ E, float* __restrict__ csinv,
                       float scale)
{
    const int bb = blockIdx.x >> 3;
    const int n0 = (blockIdx.x & 7) * 512;
    const __half* p = E + (size_t)bb * CCH * NSP + n0 + 2 * threadIdx.x;
    float s0 = 0.f, s1 = 0.f;
    for (int d = 0; d < CCH; d++) {
        float2 f = __half22float2(*(const __half2*)&p[(size_t)d * NSP]);
        s0 += f.x; s1 += f.y;
    }
    float* c = csinv + bb * NSP + n0 + 2 * threadIdx.x;
    c[0] = scale / s0;
    c[1] = scale / s1;
}

// ---------------------------------------------------------------------------
// Flat fp32 -> fp16 convert (weights only).
// ---------------------------------------------------------------------------
__global__ void cvt16(const float* __restrict__ in, __half* __restrict__ out, size_t n4)
{
    size_t stride = (size_t)gridDim.x * blockDim.x;
    const float4* in4 = (const float4*)in;
    __half2* o2 = (__half2*)out;
    for (size_t i = (size_t)blockIdx.x * blockDim.x + threadIdx.x; i < n4; i += stride) {
        float4 v = in4[i];
        o2[2 * i]     = __floats2half2_rn(v.x, v.y);
        o2[2 * i + 1] = __floats2half2_rn(v.z, v.w);
    }
}

// ---------------------------------------------------------------------------
// fp16 mma.sync (m16n8k16) GEMM, 3-stage cp.async, ldmatrix fragments.
// (R13 configuration: block 128x128x32, 8 warps 2m x 4n, warp tile 64x32,
//  static smem, 2 CTAs/SM — best measured config.)
// C[m,n] = sum_k A[m,k]*B(n,k)  (+bias[m]) (+resh fp16) (*cscale[n])
// KV: rows<512 -> E16=exp(.) ; rows>=512 -> v16. TB: B K-major via ldsm.trans.
// ---------------------------------------------------------------------------
#define STGA 10240
#define STGBT 8704

template <bool KV, bool TB, bool C_HALF, bool HAS_BIAS, bool RESH, bool CSCALE>
__global__ __launch_bounds__(256, 2)
void gemm_fp16(const __half* __restrict__ A, const __half* __restrict__ B,
               void* __restrict__ Cv, __half* __restrict__ C2,
               const float* __restrict__ bias,
               const __half* __restrict__ resh,
               const float* __restrict__ cscale, int csStride,
               int lda, int ldb, int ldc, int K,
               size_t sA, size_t sB, size_t sC, size_t sC2)
{
    constexpr int BSTG = TB ? STGBT : STGA;
    __shared__ __half As[3 * STGA / 2];
    __shared__ __half Bs[3 * BSTG / 2];

    A += (size_t)blockIdx.z * sA;
    B += (size_t)blockIdx.z * sB;
    if (RESH)   resh   += (size_t)blockIdx.z * sC;
    if (CSCALE) cscale += (size_t)blockIdx.z * csStride;

    const int tid  = threadIdx.x;
    const int lane = tid & 31;
    const int warp = tid >> 5;
    const int g = lane >> 2;
    const int t = lane & 3;
    const int wm = (warp & 1) * 64;
    const int wn = (warp >> 1) * 32;
    const int m0 = blockIdx.y * 128;
    const int n0 = blockIdx.x * 128;

    const uint32_t aBase = smem_u32(As);
    const uint32_t bBase = smem_u32(Bs);

    const uint32_t aOff = (uint32_t)(wm + (lane & 15)) * 80 + (lane >> 4) * 16;
    const uint32_t bOff = (uint32_t)(wn + (lane & 7) + ((lane >> 4) << 3)) * 80 +
                          ((lane >> 3) & 1) * 16;
    const uint32_t bOffT = (uint32_t)((lane & 7) + ((lane >> 3) & 1) * 8) * 272 +
                           (lane >> 4) * 16;

    float acc[4][4][4];
#pragma unroll
    for (int i = 0; i < 4; i++)
#pragma unroll
        for (int j = 0; j < 4; j++)
#pragma unroll
            for (int r = 0; r < 4; r++) acc[i][j][r] = 0.f;

    auto load_tile = [&](int k0, int st) {
        uint32_t ab = aBase + st * STGA;
        uint32_t bb = bBase + st * BSTG;
#pragma unroll
        for (int i = 0; i < 2; i++) {
            int id = i * 256 + tid;
            int r = id >> 2, c = id & 3;
            cp16(ab + r * 80 + c * 16, A + (size_t)(m0 + r) * lda + k0 + c * 8);
        }
#pragma unroll
        for (int i = 0; i < 2; i++) {
            int id = i * 256 + tid;
            if (TB) {
                int r = id >> 4, c = id & 15;
                cp16(bb + r * 272 + c * 16, B + (size_t)(k0 + r) * ldb + n0 + c * 8);
            } else {
                int r = id >> 2, c = id & 3;
                cp16(bb + r * 80 + c * 16, B + (size_t)(n0 + r) * ldb + k0 + c * 8);
            }
        }
        asm volatile("cp.async.commit_group;" ::: "memory");
    };

    const int T = K / 32;
    load_tile(0, 0);
    if (T > 1) load_tile(32, 1);

    for (int tt = 0; tt < T; tt++) {
        if (tt + 2 < T) asm volatile("cp.async.wait_group 1;" ::: "memory");
        else            asm volatile("cp.async.wait_group 0;" ::: "memory");
        __syncthreads();

        if (tt + 2 < T) load_tile((tt + 2) * 32, (tt + 2) % 3);

        const int st = tt % 3;
        const uint32_t sa = aBase + st * STGA;
        const uint32_t sb = bBase + st * BSTG;

#pragma unroll
        for (int kk = 0; kk < 2; kk++) {
            uint32_t af[4][4], bf[4][2];
#pragma unroll
            for (int im = 0; im < 4; im++)
                ldsm4(af[im][0], af[im][1], af[im][2], af[im][3],
                      sa + aOff + im * 1280 + kk * 32);
            if (TB) {
#pragma unroll
                for (int p = 0; p < 2; p++)
                    ldsm4t(bf[2 * p][0], bf[2 * p][1], bf[2 * p + 1][0], bf[2 * p + 1][1],
                           sb + bOffT + kk * 4352 + (wn + p * 16) * 2);
            } else {
#pragma unroll
                for (int p = 0; p < 2; p++)
                    ldsm4(bf[2 * p][0], bf[2 * p][1], bf[2 * p + 1][0], bf[2 * p + 1][1],
                          sb + bOff + p * 1280 + kk * 32);
            }
#pragma unroll
            for (int im = 0; im < 4; im++)
#pragma unroll
                for (int in = 0; in < 4; in++) {
                    asm volatile(
                        "mma.sync.aligned.m16n8k16.row.col.f32.f16.f16.f32 "
                        "{%0,%1,%2,%3},{%4,%5,%6,%7},{%8,%9},{%0,%1,%2,%3};\n"
                        : "+f"(acc[im][in][0]), "+f"(acc[im][in][1]),
                          "+f"(acc[im][in][2]), "+f"(acc[im][in][3])
                        : "r"(af[im][0]), "r"(af[im][1]), "r"(af[im][2]), "r"(af[im][3]),
                          "r"(bf[in][0]), "r"(bf[in][1]));
                }
        }
    }

    // epilogue
    const bool isv = KV && (m0 >= 512);
    const bool isk = KV && (m0 < 512);
#pragma unroll
    for (int im = 0; im < 4; im++) {
        int r0 = m0 + wm + im * 16 + g;
        int r1 = r0 + 8;
        float bv0 = HAS_BIAS ? bias[r0] : 0.f;
        float bv1 = HAS_BIAS ? bias[r1] : 0.f;
#pragma unroll
        for (int in = 0; in < 4; in++) {
            int c0 = n0 + wn + in * 8 + 2 * t;
            float v0 = acc[im][in][0] + bv0;
            float v1 = acc[im][in][1] + bv0;
            float v2 = acc[im][in][2] + bv1;
            float v3 = acc[im][in][3] + bv1;
            if (CSCALE) {
                float2 cs = *reinterpret_cast<const float2*>(&cscale[c0]);
                v0 *= cs.x; v1 *= cs.y; v2 *= cs.x; v3 *= cs.y;
            }
            if (isk) {
                v0 = __expf(v0); v1 = __expf(v1);
                v2 = __expf(v2); v3 = __expf(v3);
            }
            if (C_HALF || isv) {
                __half* C16 = ((KV && isv) ? C2 + (size_t)blockIdx.z * sC2
                                           : (__half*)Cv + (size_t)blockIdx.z * sC);
                int rr0 = isv ? r0 - 512 : r0;
                int rr1 = isv ? r1 - 512 : r1;
                *reinterpret_cast<__half2*>(&C16[(size_t)rr0 * ldc + c0]) = __floats2half2_rn(v0, v1);
                *reinterpret_cast<__half2*>(&C16[(size_t)rr1 * ldc + c0]) = __floats2half2_rn(v2, v3);
            } else {
                float* C = (float*)Cv + (size_t)blockIdx.z * sC;
                if (RESH) {
                    float2 x0 = __half22float2(*(const __half2*)&resh[(size_t)r0 * ldc + c0]);
                    float2 x1 = __half22float2(*(const __half2*)&resh[(size_t)r1 * ldc + c0]);
                    v0 += x0.x; v1 += x0.y; v2 += x1.x; v3 += x1.y;
                }
                *reinterpret_cast<float2*>(&C[(size_t)r0 * ldc + c0]) = make_float2(v0, v1);
                *reinterpret_cast<float2*>(&C[(size_t)r1 * ldc + c0]) = make_float2(v2, v3);
            }
        }
    }
}

// ---------------------------------------------------------------------------
extern "C" void kernel_launch(void* const* d_in, const int* in_sizes, int n_in,
                              void* d_out, int out_size)
{
    const float* x   = (const float*)d_in[0];
    const float* n1w = (const float*)d_in[1];
    const float* n1b = (const float*)d_in[2];
    const float* kvw = (const float*)d_in[3];
    const float* kvb = (const float*)d_in[4];
    const float* n2w = (const float*)d_in[5];
    const float* n2b = (const float*)d_in[6];
    const float* ow  = (const float*)d_in[7];
    const float* ob  = (const float*)d_in[8];
    float* out = (float*)d_out;

    float *rsinv, *csinv;
    float2 *part, *stats1, *stats2;
    unsigned *cnt1, *cnt2;
    __half *o116, *xn16, *v16, *E16, *h16, *ctx16, *w16;
    cudaGetSymbolAddress((void**)&o116,   g_o116);
    cudaGetSymbolAddress((void**)&xn16,   g_xn16);
    cudaGetSymbolAddress((void**)&v16,    g_v16);
    cudaGetSymbolAddress((void**)&E16,    g_E16);
    cudaGetSymbolAddress((void**)&h16,    g_h16);
    cudaGetSymbolAddress((void**)&ctx16,  g_ctx16);
    cudaGetSymbolAddress((void**)&rsinv,  g_rsinv);
    cudaGetSymbolAddress((void**)&csinv,  g_csinv);
    cudaGetSymbolAddress((void**)&part,   g_part);
    cudaGetSymbolAddress((void**)&stats1, g_stats1);
    cudaGetSymbolAddress((void**)&stats2, g_stats2);
    cudaGetSymbolAddress((void**)&cnt1,   g_cnt1);
    cudaGetSymbolAddress((void**)&cnt2,   g_cnt2);
    cudaGetSymbolAddress((void**)&w16,    g_w16);

    __half* kvw16 = w16;
    __half* ow16  = w16 + 1024 * 512;
    __half* x16   = h16;   // buffer reuse: x16 (step 1) / h16 (step 6) don't overlap

    const size_t sXN  = (size_t)CCH * NSP;
    const size_t sCTX = (size_t)CCH * CCH;
    const int NBLK = BATCH * NGRP * 8;  // 2048

    // 0. weight converts
    cvt16<<<256, 256>>>(kvw, kvw16, (1024 * 512) / 4);
    cvt16<<<128, 256>>>(ow,  ow16,  (512 * 512) / 4);

    // 1. GroupNorm1: stats (fp32, + emit x16) then normalize from x16 -> xn16
    gstats32<<<NBLK, 256>>>(x, x16, part, stats1, cnt1);
    gnorm16<0><<<NBLK, 256>>>(x16, n1w, n1b, stats1, xn16);

    // 2. kv GEMM (TB, KV): E16 = exp(k+bias); v16 split. M=1024,N=4096,K=512
    gemm_fp16<true, true, true, true, false, false>
        <<<dim3(NSP / 128, 1024 / 128, BATCH), 256>>>(
        kvw16, xn16, E16, v16, kvb, nullptr, nullptr, 0,
        CCH, NSP, NSP, CCH, 0, sXN, sXN, sXN);

    // 3. rowsum -> 1/sum ; colsum -> scale/sum
    rowsum_k<<<BATCH * CCH, 256>>>(E16, rsinv);
    colsum<<<BATCH * 8, 256>>>(E16, csinv, 0.044194173824159216f);

    // 4. ctx2[e,d] = (sum_n v[e,n]*E[d,n]) * rsinv[d]  -> fp16
    gemm_fp16<false, false, true, false, false, true>
        <<<dim3(CCH / 128, CCH / 128, BATCH), 256>>>(
        v16, E16, ctx16, nullptr, nullptr, nullptr, rsinv, CCH,
        NSP, NSP, CCH, NSP, sXN, sXN, sCTX, 0);

    // 5. o1[e,n] = (sum_d ctx2[e,d]*E[d,n]) * csinv[n]  -> fp16 (TB + CSCALE)
    gemm_fp16<false, true, true, false, false, true>
        <<<dim3(NSP / 128, CCH / 128, BATCH), 256>>>(
        ctx16, E16, o116, nullptr, nullptr, nullptr, csinv, NSP,
        CCH, NSP, NSP, CCH, sCTX, sXN, sXN, 0);

    // 6. h = gelu(GN2(o1)) -> h16 (stats fused; h16 overwrites x16, now dead)
    gstats16<<<NBLK, 256>>>(o116, part, stats2, cnt2);
    gnorm16<1><<<NBLK, 256>>>(o116, n2w, n2b, stats2, h16);

    // 7. out = W_out @ h + b_out + xn16 (fp16 residual)
    gemm_fp16<false, true, false, true, true, false>
        <<<dim3(NSP / 128, CCH / 128, BATCH), 256>>>(
        ow16, h16, out, nullptr, ob, xn16, nullptr, 0,
        CCH, NSP, NSP, CCH, 0, sXN, sXN, 0);
}